// round 8
// baseline (speedup 1.0000x reference)
#include <cuda_runtime.h>
#include <cuda_bf16.h>
#include <stdint.h>
#include <math.h>

// Problem constants
#define BB 2
#define TT 2048
#define CC 1024
#define HH 16
#define HD 64
#define MROWS (BB*TT)

// ---------------------------------------------------------------------------
// Scratch (allocation-free rule: __device__ globals)
// ---------------------------------------------------------------------------
__device__ __nv_bfloat16 g_xh  [MROWS*CC];
__device__ __nv_bfloat16 g_xl  [MROWS*CC];
__device__ __nv_bfloat16 g_qkvh[3*MROWS*CC];   // [q|k|v][B,H,T,HD]
__device__ __nv_bfloat16 g_qkvl[3*MROWS*CC];
__device__ __nv_bfloat16 g_aoh [MROWS*CC];
__device__ __nv_bfloat16 g_aol [MROWS*CC];
__device__ __nv_bfloat16 g_wt  [8*CC*CC];      // [w*2+{hi,lo}][n][k]  (W^T, K-major)

// ---------------------------------------------------------------------------
// Warp-MMA helpers (base sm_80+ features)
// ---------------------------------------------------------------------------
__device__ __forceinline__ uint32_t s2u(const void* p) {
    uint32_t a;
    asm("{ .reg .u64 t; cvta.to.shared.u64 t, %1; cvt.u32.u64 %0, t; }"
        : "=r"(a) : "l"(p));
    return a;
}
__device__ __forceinline__ void ldsm_x4(uint32_t* r, uint32_t addr) {
    asm volatile("ldmatrix.sync.aligned.m8n8.x4.shared.b16 {%0,%1,%2,%3}, [%4];"
        : "=r"(r[0]), "=r"(r[1]), "=r"(r[2]), "=r"(r[3]) : "r"(addr));
}
__device__ __forceinline__ void ldsm_x4t(uint32_t* r, uint32_t addr) {
    asm volatile("ldmatrix.sync.aligned.m8n8.x4.trans.shared.b16 {%0,%1,%2,%3}, [%4];"
        : "=r"(r[0]), "=r"(r[1]), "=r"(r[2]), "=r"(r[3]) : "r"(addr));
}
__device__ __forceinline__ void mma16816(float* c, const uint32_t* a, const uint32_t* b) {
    asm volatile(
        "mma.sync.aligned.m16n8k16.row.col.f32.bf16.bf16.f32 "
        "{%0,%1,%2,%3}, {%4,%5,%6,%7}, {%8,%9}, {%0,%1,%2,%3};"
        : "+f"(c[0]), "+f"(c[1]), "+f"(c[2]), "+f"(c[3])
        : "r"(a[0]), "r"(a[1]), "r"(a[2]), "r"(a[3]), "r"(b[0]), "r"(b[1]));
}
__device__ __forceinline__ void cpa16(uint32_t dst, const void* src) {
    asm volatile("cp.async.ca.shared.global [%0], [%1], 16;" :: "r"(dst), "l"(src));
}
#define CP_COMMIT() asm volatile("cp.async.commit_group;" ::: "memory")
#define CP_WAIT(n)  asm volatile("cp.async.wait_group %0;" :: "n"(n) : "memory")

__device__ __forceinline__ void split1(float v, __nv_bfloat16& h, __nv_bfloat16& l) {
    h = __float2bfloat16_rn(v);
    l = __float2bfloat16_rn(v - __bfloat162float(h));
}
__device__ __forceinline__ uint32_t pk2(__nv_bfloat16 a, __nv_bfloat16 b) {
    return (uint32_t)__bfloat16_as_ushort(a) | ((uint32_t)__bfloat16_as_ushort(b) << 16);
}
__device__ __forceinline__ void splitpack(float a, float b, uint32_t& hi, uint32_t& lo) {
    __nv_bfloat16 ah, al, bh, bl;
    split1(a, ah, al); split1(b, bh, bl);
    hi = pk2(ah, bh); lo = pk2(al, bl);
}

// ---------------------------------------------------------------------------
// Prep kernels
// ---------------------------------------------------------------------------
__global__ void splitx(const float* __restrict__ x,
                       __nv_bfloat16* __restrict__ hi, __nv_bfloat16* __restrict__ lo)
{
    const int i = blockIdx.x * blockDim.x + threadIdx.x;
    float4 v = ((const float4*)x)[i];
    __nv_bfloat16 h0,h1,h2,h3,l0,l1,l2,l3;
    split1(v.x,h0,l0); split1(v.y,h1,l1); split1(v.z,h2,l2); split1(v.w,h3,l3);
    uint2 hw = { pk2(h0,h1), pk2(h2,h3) };
    uint2 lw = { pk2(l0,l1), pk2(l2,l3) };
    ((uint2*)hi)[i] = hw;
    ((uint2*)lo)[i] = lw;
}

// all 4 weight transposes+splits in one launch (z picks the weight)
__global__ __launch_bounds__(256)
void wsplit4(const float* __restrict__ W0, const float* __restrict__ W1,
             const float* __restrict__ W2, const float* __restrict__ W3,
             __nv_bfloat16* __restrict__ wt)
{
    __shared__ float t[32][33];
    const int wsel = blockIdx.z;
    const float* W = (wsel == 0) ? W0 : (wsel == 1) ? W1 : (wsel == 2) ? W2 : W3;
    __nv_bfloat16* th = wt + (size_t)(2 * wsel)     * CC * CC;
    __nv_bfloat16* tl = wt + (size_t)(2 * wsel + 1) * CC * CC;

    const int n0 = blockIdx.x * 32;
    const int k0 = blockIdx.y * 32;
    const int tx = threadIdx.x & 31;
    const int ty = threadIdx.x >> 5;
#pragma unroll
    for (int r = 0; r < 4; r++) {
        const int row = ty + r * 8;
        t[row][tx] = W[(size_t)(k0 + row) * CC + n0 + tx];
    }
    __syncthreads();
#pragma unroll
    for (int r = 0; r < 4; r++) {
        const int row = ty + r * 8;
        const float v = t[tx][row];
        __nv_bfloat16 h, l;
        split1(v, h, l);
        th[(size_t)(n0 + row) * CC + k0 + tx] = h;
        tl[(size_t)(n0 + row) * CC + k0 + tx] = l;
    }
}

// ---------------------------------------------------------------------------
// mma.sync split-bf16 GEMM, low-register variant (no spills):
// CTA tile 64(M) x 128(N), 8 warps (2m x 4n), warp tile 32x32, acc=32 regs.
// 4-stage cp.async pipeline, 2 CTAs/SM.
// MODE 1 (fused QKV): N=3072 (3 weights), bf16 hi/lo permuted out.
// MODE 0 (out proj):  N=1024, fp32 out.
// ---------------------------------------------------------------------------
#define KC 16
#define TSTRIDE 48
#define A_TILE_B (64*TSTRIDE)            // 3072  (Ah or Al)
#define B_TILE_B (128*TSTRIDE)           // 6144  (Bh or Bl)
#define STAGE_B (2*A_TILE_B + 2*B_TILE_B) // 18432
#define GEMM_SMEM (4*STAGE_B)            // 73728

template<int MODE>
__global__ __launch_bounds__(256, 2)
void mmagemm(const __nv_bfloat16* __restrict__ Ah, const __nv_bfloat16* __restrict__ Al,
             const __nv_bfloat16* __restrict__ Wt,
             const float* __restrict__ b0, const float* __restrict__ b1,
             const float* __restrict__ b2,
             float* __restrict__ Y,
             __nv_bfloat16* __restrict__ Yh, __nv_bfloat16* __restrict__ Yl)
{
    extern __shared__ char dsm[];
    const uint32_t sb = s2u(dsm);

    const int tid = threadIdx.x;
    const int lane = tid & 31;
    const int wid = tid >> 5;
    const int warp_m = wid & 1;          // 0..1 (32 rows each)
    const int warp_n = wid >> 1;         // 0..3 (32 cols each)
    const int bm = blockIdx.y * 64;
    const int bn = blockIdx.x * 128;

    const int which = (MODE == 1) ? (bn >> 10) : 0;
    const int nw = bn & (CC - 1);
    const __nv_bfloat16* Bh = Wt + (size_t)(2 * which)     * CC * CC;
    const __nv_bfloat16* Bl = Wt + (size_t)(2 * which + 1) * CC * CC;
    const float* bias = (MODE == 0) ? b0 : (which == 0) ? b0 : (which == 1) ? b1 : b2;
    const float scale = (MODE == 1 && which == 0) ? 0.125f : 1.0f;

    float acc[2][4][4];
#pragma unroll
    for (int i = 0; i < 2; i++)
#pragma unroll
        for (int j = 0; j < 4; j++)
#pragma unroll
            for (int q = 0; q < 4; q++) acc[i][j][q] = 0.f;

    // per-stage cp.async: 768 x 16B ops; thread does 3.
    //   i=0: Ah (tid<128) / Al (tid>=128), 64 rows x 2 segs each
    //   i=1: Bh 128 rows x 2 segs;  i=2: Bl
    auto issue = [&](int c) {
        const int k0 = c * KC;
        const uint32_t bu = sb + (c & 3) * STAGE_B;
        {   // A tiles
            const int local = tid & 127;
            const int row = local >> 1;
            const int seg = local & 1;
            const __nv_bfloat16* s = (tid < 128) ? Ah : Al;
            const uint32_t dbase = (tid < 128) ? 0u : (uint32_t)A_TILE_B;
            cpa16(bu + dbase + row * TSTRIDE + seg * 16,
                  s + (size_t)(bm + row) * CC + k0 + seg * 8);
        }
        {   // Bh
            const int row = tid >> 1;
            const int seg = tid & 1;
            cpa16(bu + 2*A_TILE_B + row * TSTRIDE + seg * 16,
                  Bh + (size_t)(nw + row) * CC + k0 + seg * 8);
        }
        {   // Bl
            const int row = tid >> 1;
            const int seg = tid & 1;
            cpa16(bu + 2*A_TILE_B + B_TILE_B + row * TSTRIDE + seg * 16,
                  Bl + (size_t)(nw + row) * CC + k0 + seg * 8);
        }
        CP_COMMIT();
    };

    issue(0); issue(1); issue(2);

    const uint32_t a_off = (uint32_t)((warp_m * 32 + (lane & 15)) * TSTRIDE
                                      + (lane >> 4) * 16);
    const uint32_t b_off = (uint32_t)((warp_n * 32 + ((lane >> 4) * 8) + (lane & 7)) * TSTRIDE
                                      + ((lane >> 3) & 1) * 16);

    for (int c = 0; c < 64; c++) {
        CP_WAIT(2);
        __syncthreads();
        if (c + 3 < 64) issue(c + 3);

        const uint32_t bu = sb + (c & 3) * STAGE_B;
        uint32_t af[2][4];
        uint32_t bhf[2][4], blf[2][4];

#pragma unroll
        for (int p = 0; p < 2; p++) {
            ldsm_x4(bhf[p], bu + 2*A_TILE_B + b_off + (uint32_t)(p * 16 * TSTRIDE));
            ldsm_x4(blf[p], bu + 2*A_TILE_B + B_TILE_B + b_off + (uint32_t)(p * 16 * TSTRIDE));
        }
#pragma unroll
        for (int mt = 0; mt < 2; mt++)
            ldsm_x4(af[mt], bu + a_off + (uint32_t)(mt * 16 * TSTRIDE));    // Ah
#pragma unroll
        for (int mt = 0; mt < 2; mt++)
#pragma unroll
            for (int nt = 0; nt < 4; nt++)
                mma16816(acc[mt][nt], af[mt], &bhf[nt >> 1][(nt & 1) * 2]);
#pragma unroll
        for (int mt = 0; mt < 2; mt++)
#pragma unroll
            for (int nt = 0; nt < 4; nt++)
                mma16816(acc[mt][nt], af[mt], &blf[nt >> 1][(nt & 1) * 2]);
#pragma unroll
        for (int mt = 0; mt < 2; mt++)
            ldsm_x4(af[mt], bu + A_TILE_B + a_off + (uint32_t)(mt * 16 * TSTRIDE)); // Al
#pragma unroll
        for (int mt = 0; mt < 2; mt++)
#pragma unroll
            for (int nt = 0; nt < 4; nt++)
                mma16816(acc[mt][nt], af[mt], &bhf[nt >> 1][(nt & 1) * 2]);
    }

#pragma unroll
    for (int mt = 0; mt < 2; mt++) {
#pragma unroll
        for (int nt = 0; nt < 4; nt++) {
            const int m0 = bm + warp_m * 32 + mt * 16 + (lane >> 2);
            const int nn = nw + warp_n * 32 + nt * 8 + 2 * (lane & 3);
            const float bb0 = __ldg(bias + nn);
            const float bb1 = __ldg(bias + nn + 1);
#pragma unroll
            for (int half = 0; half < 2; half++) {
                const int m = m0 + half * 8;
                const int bb = m >> 11;
                const int tt = m & (TT - 1);
                const float v0 = (acc[mt][nt][half * 2 + 0] + bb0) * scale;
                const float v1 = (acc[mt][nt][half * 2 + 1] + bb1) * scale;
                if (MODE == 0) {
                    float2 r; r.x = v0; r.y = v1;
                    *(float2*)(Y + (size_t)m * CC + nn) = r;
                } else {
                    const int h = nn >> 6;
                    const int d = nn & (HD - 1);
                    const size_t dst = (size_t)which * MROWS * CC
                                     + (((size_t)bb * HH + h) * TT + tt) * HD + d;
                    uint32_t hw, lw;
                    splitpack(v0, v1, hw, lw);
                    *(uint32_t*)(Yh + dst) = hw;
                    *(uint32_t*)(Yl + dst) = lw;
                }
            }
        }
    }
}

// ---------------------------------------------------------------------------
// flash3: FA2-style mma.sync causal attention, split-bf16, 3-stage KV pipeline.
// (unchanged from round 7)
// ---------------------------------------------------------------------------
#define RS 144
#define QTILE_B (128*RS)
#define KVTILE_B (64*RS)
#define KVBUF_B (4*KVTILE_B)
#define FL_SMEM (2*QTILE_B + 3*KVBUF_B)

__global__ __launch_bounds__(256, 1)
void flash3(const __nv_bfloat16* __restrict__ Qh, const __nv_bfloat16* __restrict__ Ql,
            const __nv_bfloat16* __restrict__ Kh, const __nv_bfloat16* __restrict__ Kl,
            const __nv_bfloat16* __restrict__ Vh, const __nv_bfloat16* __restrict__ Vl)
{
    extern __shared__ char sm[];
    const uint32_t sb = s2u(sm);
    const uint32_t kvb = sb + 2 * QTILE_B;

    const int tid = threadIdx.x;
    const int lane = tid & 31;
    const int wid = tid >> 5;
    const int qt = blockIdx.x;
    const int h  = blockIdx.y;
    const int b  = blockIdx.z;
    const size_t head = ((size_t)b * HH + h) * TT * HD;

#pragma unroll
    for (int i = 0; i < 8; i++) {
        const int idx = i * 256 + tid;
        const int tile = idx >> 10;
        const int row = (idx >> 3) & 127;
        const int seg = idx & 7;
        const __nv_bfloat16* src = (tile == 0) ? Qh : Ql;
        cpa16(sb + tile * QTILE_B + row * RS + seg * 16,
              src + head + (size_t)(qt * 128 + row) * HD + seg * 8);
    }
    CP_COMMIT();

    auto issue_kv = [&](int t) {
        const int kv0 = t * 64;
        const uint32_t bu = kvb + (t % 3) * KVBUF_B;
#pragma unroll
        for (int i = 0; i < 8; i++) {
            const int idx = i * 256 + tid;
            const int tile = idx >> 9;
            const int row = (idx >> 3) & 63;
            const int seg = idx & 7;
            const __nv_bfloat16* src = (tile == 0) ? Kh : (tile == 1) ? Kl
                                      : (tile == 2) ? Vh : Vl;
            cpa16(bu + tile * KVTILE_B + row * RS + seg * 16,
                  src + head + (size_t)(kv0 + row) * HD + seg * 8);
        }
        CP_COMMIT();
    };

    const int ntiles = (qt + 1) * 2;
    issue_kv(0);
    if (1 < ntiles) issue_kv(1);

    CP_WAIT(2);
    __syncthreads();

    uint32_t qhf[4][4], qlf[4][4];
    {
        const uint32_t qaddr = sb + (uint32_t)((wid * 16 + (lane & 15)) * RS
                                               + (lane >> 4) * 16);
#pragma unroll
        for (int ck = 0; ck < 4; ck++) {
            ldsm_x4(qhf[ck], qaddr + ck * 32);
            ldsm_x4(qlf[ck], qaddr + QTILE_B + ck * 32);
        }
    }

    float m0 = -1e30f, m1 = -1e30f, l0 = 0.f, l1 = 0.f;
    float oacc[8][4];
#pragma unroll
    for (int nt = 0; nt < 8; nt++)
#pragma unroll
        for (int e = 0; e < 4; e++) oacc[nt][e] = 0.f;

    const int qrow = qt * 128 + wid * 16 + (lane >> 2);

    for (int t = 0; t < ntiles; t++) {
        if (t + 1 < ntiles) CP_WAIT(1);
        else                CP_WAIT(0);
        __syncthreads();
        if (t + 2 < ntiles) issue_kv(t + 2);

        const uint32_t bu = kvb + (t % 3) * KVBUF_B;

        float sacc[8][4];
#pragma unroll
        for (int nt = 0; nt < 8; nt++)
#pragma unroll
            for (int e = 0; e < 4; e++) sacc[nt][e] = 0.f;

#pragma unroll
        for (int nt = 0; nt < 8; nt++) {
            const uint32_t ka = bu + (uint32_t)((nt * 8 + (lane & 7)) * RS
                                                + (lane >> 3) * 16);
            uint32_t khf[8], klf[8];
            ldsm_x4(khf, ka);            ldsm_x4(khf + 4, ka + 64);
            ldsm_x4(klf, ka + KVTILE_B); ldsm_x4(klf + 4, ka + KVTILE_B + 64);
#pragma unroll
            for (int ck = 0; ck < 4; ck++) {
                mma16816(sacc[nt], qhf[ck], &khf[ck * 2]);
                mma16816(sacc[nt], qhf[ck], &klf[ck * 2]);
                mma16816(sacc[nt], qlf[ck], &khf[ck * 2]);
            }
        }

        if (t >= ntiles - 2) {
            const int kv0 = t * 64;
#pragma unroll
            for (int nt = 0; nt < 8; nt++)
#pragma unroll
                for (int e = 0; e < 4; e++) {
                    const int key = kv0 + nt * 8 + 2 * (lane & 3) + (e & 1);
                    const int row = qrow + ((e & 2) ? 8 : 0);
                    if (key > row) sacc[nt][e] = -1e30f;
                }
        }

#pragma unroll
        for (int hh = 0; hh < 2; hh++) {
            float& mprev = hh ? m1 : m0;
            float& lsum  = hh ? l1 : l0;
            float mx = -1e30f;
#pragma unroll
            for (int nt = 0; nt < 8; nt++)
                mx = fmaxf(mx, fmaxf(sacc[nt][hh*2], sacc[nt][hh*2+1]));
            mx = fmaxf(mx, __shfl_xor_sync(0xffffffffu, mx, 1));
            mx = fmaxf(mx, __shfl_xor_sync(0xffffffffu, mx, 2));
            const float mn = fmaxf(mprev, mx);
            const float alpha = __expf(mprev - mn);
            mprev = mn;
            float ps = 0.f;
#pragma unroll
            for (int nt = 0; nt < 8; nt++) {
                const float p0 = __expf(sacc[nt][hh*2]   - mn);
                const float p1 = __expf(sacc[nt][hh*2+1] - mn);
                ps += p0 + p1;
                sacc[nt][hh*2]   = p0;
                sacc[nt][hh*2+1] = p1;
                oacc[nt][hh*2]   *= alpha;
                oacc[nt][hh*2+1] *= alpha;
            }
            lsum = lsum * alpha + ps;
        }

        uint32_t aph[4][4], apl[4][4];
#pragma unroll
        for (int ck = 0; ck < 4; ck++) {
            splitpack(sacc[2*ck][0],   sacc[2*ck][1],   aph[ck][0], apl[ck][0]);
            splitpack(sacc[2*ck][2],   sacc[2*ck][3],   aph[ck][1], apl[ck][1]);
            splitpack(sacc[2*ck+1][0], sacc[2*ck+1][1], aph[ck][2], apl[ck][2]);
            splitpack(sacc[2*ck+1][2], sacc[2*ck+1][3], aph[ck][3], apl[ck][3]);
        }

#pragma unroll
        for (int nt = 0; nt < 8; nt++) {
            const uint32_t va = bu + 2 * KVTILE_B + (uint32_t)(lane * RS + nt * 16);
            uint32_t vhf[8], vlf[8];
            ldsm_x4t(vhf, va);            ldsm_x4t(vhf + 4, va + 32 * RS);
            ldsm_x4t(vlf, va + KVTILE_B); ldsm_x4t(vlf + 4, va + KVTILE_B + 32 * RS);
#pragma unroll
            for (int ck = 0; ck < 4; ck++) {
                mma16816(oacc[nt], aph[ck], &vhf[ck * 2]);
                mma16816(oacc[nt], aph[ck], &vlf[ck * 2]);
                mma16816(oacc[nt], apl[ck], &vhf[ck * 2]);
            }
        }
    }

    l0 += __shfl_xor_sync(0xffffffffu, l0, 1);
    l0 += __shfl_xor_sync(0xffffffffu, l0, 2);
    l1 += __shfl_xor_sync(0xffffffffu, l1, 1);
    l1 += __shfl_xor_sync(0xffffffffu, l1, 2);
    const float inv0 = 1.f / l0;
    const float inv1 = 1.f / l1;

#pragma unroll
    for (int nt = 0; nt < 8; nt++) {
        const int d = nt * 8 + 2 * (lane & 3);
#pragma unroll
        for (int hh = 0; hh < 2; hh++) {
            const int row = qrow + hh * 8;
            const float inv = hh ? inv1 : inv0;
            const float v0 = oacc[nt][hh*2]   * inv;
            const float v1 = oacc[nt][hh*2+1] * inv;
            uint32_t hw, lw;
            splitpack(v0, v1, hw, lw);
            const size_t dst = ((size_t)(b * TT + row)) * CC + h * HD + d;
            *(uint32_t*)(g_aoh + dst) = hw;
            *(uint32_t*)(g_aol + dst) = lw;
        }
    }
}

// ---------------------------------------------------------------------------
extern "C" void kernel_launch(void* const* d_in, const int* in_sizes, int n_in,
                              void* d_out, int out_size)
{
    const float* x  = (const float*)d_in[0];
    const float* Wq = (const float*)d_in[1];
    const float* bq = (const float*)d_in[2];
    const float* Wk = (const float*)d_in[3];
    const float* bk = (const float*)d_in[4];
    const float* Wv = (const float*)d_in[5];
    const float* bv = (const float*)d_in[6];
    const float* Wo = (const float*)d_in[7];
    const float* bo = (const float*)d_in[8];
    float* out = (float*)d_out;

    __nv_bfloat16 *xh, *xl, *qkvh, *qkvl, *aoh, *aol, *wt;
    cudaGetSymbolAddress((void**)&xh,   g_xh);
    cudaGetSymbolAddress((void**)&xl,   g_xl);
    cudaGetSymbolAddress((void**)&qkvh, g_qkvh);
    cudaGetSymbolAddress((void**)&qkvl, g_qkvl);
    cudaGetSymbolAddress((void**)&aoh,  g_aoh);
    cudaGetSymbolAddress((void**)&aol,  g_aol);
    cudaGetSymbolAddress((void**)&wt,   g_wt);

    static bool attr_set = false;
    if (!attr_set) {
        cudaFuncSetAttribute(mmagemm<0>, cudaFuncAttributeMaxDynamicSharedMemorySize, GEMM_SMEM);
        cudaFuncSetAttribute(mmagemm<1>, cudaFuncAttributeMaxDynamicSharedMemorySize, GEMM_SMEM);
        cudaFuncSetAttribute(flash3, cudaFuncAttributeMaxDynamicSharedMemorySize, FL_SMEM);
        attr_set = true;
    }

    const int n4 = MROWS * CC / 4;
    splitx<<<n4 / 256, 256>>>(x, xh, xl);

    dim3 wgrid(CC / 32, CC / 32, 4);
    wsplit4<<<wgrid, 256>>>(Wq, Wk, Wv, Wo, wt);

    // fused QKV projection (N = 3072), CTA tile 64x128
    dim3 qkv_grid(3 * CC / 128, MROWS / 64);    // (24, 64)
    mmagemm<1><<<qkv_grid, 256, GEMM_SMEM>>>(xh, xl, wt, bq, bk, bv,
                                             nullptr, qkvh, qkvl);

    dim3 att_grid(TT / 128, HH, BB);
    flash3<<<att_grid, 256, FL_SMEM>>>(qkvh, qkvl,
                                       qkvh + (size_t)MROWS*CC, qkvl + (size_t)MROWS*CC,
                                       qkvh + 2*(size_t)MROWS*CC, qkvl + 2*(size_t)MROWS*CC);

    // output projection (N = 1024)
    dim3 out_grid(CC / 128, MROWS / 64);        // (8, 64)
    mmagemm<0><<<out_grid, 256, GEMM_SMEM>>>(aoh, aol, wt + 6*(size_t)CC*CC,
                                             bo, nullptr, nullptr,
                                             out, nullptr, nullptr);
}

// round 9
// speedup vs baseline: 1.0156x; 1.0156x over previous
#include <cuda_runtime.h>
#include <cuda_bf16.h>
#include <stdint.h>
#include <math.h>

// Problem constants
#define BB 2
#define TT 2048
#define CC 1024
#define HH 16
#define HD 64
#define MROWS (BB*TT)

// ---------------------------------------------------------------------------
// Scratch (allocation-free rule: __device__ globals)
// ---------------------------------------------------------------------------
__device__ __nv_bfloat16 g_xh  [MROWS*CC];
__device__ __nv_bfloat16 g_xl  [MROWS*CC];
__device__ __nv_bfloat16 g_qkvh[3*MROWS*CC];   // [q|k|v][B,H,T,HD]
__device__ __nv_bfloat16 g_qkvl[3*MROWS*CC];
__device__ __nv_bfloat16 g_aoh [MROWS*CC];
__device__ __nv_bfloat16 g_aol [MROWS*CC];
__device__ __nv_bfloat16 g_wt  [8*CC*CC];      // [w*2+{hi,lo}][n][k]  (W^T, K-major)

// ---------------------------------------------------------------------------
// Warp-MMA helpers (base sm_80+ features)
// ---------------------------------------------------------------------------
__device__ __forceinline__ uint32_t s2u(const void* p) {
    uint32_t a;
    asm("{ .reg .u64 t; cvta.to.shared.u64 t, %1; cvt.u32.u64 %0, t; }"
        : "=r"(a) : "l"(p));
    return a;
}
__device__ __forceinline__ void ldsm_x4(uint32_t* r, uint32_t addr) {
    asm volatile("ldmatrix.sync.aligned.m8n8.x4.shared.b16 {%0,%1,%2,%3}, [%4];"
        : "=r"(r[0]), "=r"(r[1]), "=r"(r[2]), "=r"(r[3]) : "r"(addr));
}
__device__ __forceinline__ void ldsm_x4t(uint32_t* r, uint32_t addr) {
    asm volatile("ldmatrix.sync.aligned.m8n8.x4.trans.shared.b16 {%0,%1,%2,%3}, [%4];"
        : "=r"(r[0]), "=r"(r[1]), "=r"(r[2]), "=r"(r[3]) : "r"(addr));
}
__device__ __forceinline__ void mma16816(float* c, const uint32_t* a, const uint32_t* b) {
    asm volatile(
        "mma.sync.aligned.m16n8k16.row.col.f32.bf16.bf16.f32 "
        "{%0,%1,%2,%3}, {%4,%5,%6,%7}, {%8,%9}, {%0,%1,%2,%3};"
        : "+f"(c[0]), "+f"(c[1]), "+f"(c[2]), "+f"(c[3])
        : "r"(a[0]), "r"(a[1]), "r"(a[2]), "r"(a[3]), "r"(b[0]), "r"(b[1]));
}
__device__ __forceinline__ void cpa16(uint32_t dst, const void* src) {
    asm volatile("cp.async.ca.shared.global [%0], [%1], 16;" :: "r"(dst), "l"(src));
}
#define CP_COMMIT() asm volatile("cp.async.commit_group;" ::: "memory")
#define CP_WAIT(n)  asm volatile("cp.async.wait_group %0;" :: "n"(n) : "memory")

__device__ __forceinline__ void split1(float v, __nv_bfloat16& h, __nv_bfloat16& l) {
    h = __float2bfloat16_rn(v);
    l = __float2bfloat16_rn(v - __bfloat162float(h));
}
__device__ __forceinline__ uint32_t pk2(__nv_bfloat16 a, __nv_bfloat16 b) {
    return (uint32_t)__bfloat16_as_ushort(a) | ((uint32_t)__bfloat16_as_ushort(b) << 16);
}
__device__ __forceinline__ void splitpack(float a, float b, uint32_t& hi, uint32_t& lo) {
    __nv_bfloat16 ah, al, bh, bl;
    split1(a, ah, al); split1(b, bh, bl);
    hi = pk2(ah, bh); lo = pk2(al, bl);
}

// ---------------------------------------------------------------------------
// Prep kernels
// ---------------------------------------------------------------------------
__global__ void splitx(const float* __restrict__ x,
                       __nv_bfloat16* __restrict__ hi, __nv_bfloat16* __restrict__ lo)
{
    const int i = blockIdx.x * blockDim.x + threadIdx.x;
    float4 v = ((const float4*)x)[i];
    __nv_bfloat16 h0,h1,h2,h3,l0,l1,l2,l3;
    split1(v.x,h0,l0); split1(v.y,h1,l1); split1(v.z,h2,l2); split1(v.w,h3,l3);
    uint2 hw = { pk2(h0,h1), pk2(h2,h3) };
    uint2 lw = { pk2(l0,l1), pk2(l2,l3) };
    ((uint2*)hi)[i] = hw;
    ((uint2*)lo)[i] = lw;
}

__global__ __launch_bounds__(256)
void wsplit4(const float* __restrict__ W0, const float* __restrict__ W1,
             const float* __restrict__ W2, const float* __restrict__ W3,
             __nv_bfloat16* __restrict__ wt)
{
    __shared__ float t[32][33];
    const int wsel = blockIdx.z;
    const float* W = (wsel == 0) ? W0 : (wsel == 1) ? W1 : (wsel == 2) ? W2 : W3;
    __nv_bfloat16* th = wt + (size_t)(2 * wsel)     * CC * CC;
    __nv_bfloat16* tl = wt + (size_t)(2 * wsel + 1) * CC * CC;

    const int n0 = blockIdx.x * 32;
    const int k0 = blockIdx.y * 32;
    const int tx = threadIdx.x & 31;
    const int ty = threadIdx.x >> 5;
#pragma unroll
    for (int r = 0; r < 4; r++) {
        const int row = ty + r * 8;
        t[row][tx] = W[(size_t)(k0 + row) * CC + n0 + tx];
    }
    __syncthreads();
#pragma unroll
    for (int r = 0; r < 4; r++) {
        const int row = ty + r * 8;
        const float v = t[tx][row];
        __nv_bfloat16 h, l;
        split1(v, h, l);
        th[(size_t)(n0 + row) * CC + k0 + tx] = h;
        tl[(size_t)(n0 + row) * CC + k0 + tx] = l;
    }
}

// ---------------------------------------------------------------------------
// mma.sync split-bf16 GEMM — ROUND 7 CONFIG (128x128 CTA tile, 4 stages).
// MODE 1 (fused QKV): N=3072, bf16 hi/lo permuted out. MODE 0: fp32 out.
// ---------------------------------------------------------------------------
#define KC 16
#define TSTRIDE 48
#define TILE_B (128*TSTRIDE)
#define BUF_B  (4*TILE_B)            // 24576
#define GEMM_SMEM (4*BUF_B)          // 98304

template<int MODE>
__global__ __launch_bounds__(256, 2)
void mmagemm(const __nv_bfloat16* __restrict__ Ah, const __nv_bfloat16* __restrict__ Al,
             const __nv_bfloat16* __restrict__ Wt,
             const float* __restrict__ b0, const float* __restrict__ b1,
             const float* __restrict__ b2,
             float* __restrict__ Y,
             __nv_bfloat16* __restrict__ Yh, __nv_bfloat16* __restrict__ Yl)
{
    extern __shared__ char dsm[];
    const uint32_t sb = s2u(dsm);

    const int tid = threadIdx.x;
    const int lane = tid & 31;
    const int wid = tid >> 5;
    const int warp_m = wid & 1;
    const int warp_n = wid >> 1;
    const int bm = blockIdx.y * 128;
    const int bn = blockIdx.x * 128;

    const int which = (MODE == 1) ? (bn >> 10) : 0;
    const int nw = bn & (CC - 1);
    const __nv_bfloat16* Bh = Wt + (size_t)(2 * which)     * CC * CC;
    const __nv_bfloat16* Bl = Wt + (size_t)(2 * which + 1) * CC * CC;
    const float* bias = (MODE == 0) ? b0 : (which == 0) ? b0 : (which == 1) ? b1 : b2;
    const float scale = (MODE == 1 && which == 0) ? 0.125f : 1.0f;

    float acc[4][4][4];
#pragma unroll
    for (int i = 0; i < 4; i++)
#pragma unroll
        for (int j = 0; j < 4; j++)
#pragma unroll
            for (int q = 0; q < 4; q++) acc[i][j][q] = 0.f;

    auto issue = [&](int c) {
        const int k0 = c * KC;
        const uint32_t bu = sb + (c & 3) * BUF_B;
#pragma unroll
        for (int i = 0; i < 4; i++) {
            const int j = i * 256 + tid;
            const int row = (j >> 1) & 127;
            const int seg = j & 1;
            const __nv_bfloat16* s = (i == 0) ? Ah : (i == 1) ? Al : (i == 2) ? Bh : Bl;
            const int rb = (i < 2) ? bm : nw;
            cpa16(bu + i * TILE_B + row * TSTRIDE + seg * 16,
                  s + (size_t)(rb + row) * CC + k0 + seg * 8);
        }
        CP_COMMIT();
    };

    issue(0); issue(1); issue(2);

    const uint32_t a_off = (uint32_t)((warp_m * 64 + (lane & 15)) * TSTRIDE
                                      + (lane >> 4) * 16);
    const uint32_t b_off = (uint32_t)((warp_n * 32 + ((lane >> 4) * 8) + (lane & 7)) * TSTRIDE
                                      + ((lane >> 3) & 1) * 16);

    for (int c = 0; c < 64; c++) {
        CP_WAIT(2);
        __syncthreads();
        if (c + 3 < 64) issue(c + 3);

        const uint32_t bu = sb + (c & 3) * BUF_B;
        uint32_t af[4][4];
        uint32_t bhf[2][4], blf[2][4];

#pragma unroll
        for (int p = 0; p < 2; p++) {
            ldsm_x4(bhf[p], bu + 2*TILE_B + b_off + (uint32_t)(p * 16 * TSTRIDE));
            ldsm_x4(blf[p], bu + 3*TILE_B + b_off + (uint32_t)(p * 16 * TSTRIDE));
        }
#pragma unroll
        for (int mt = 0; mt < 4; mt++)
            ldsm_x4(af[mt], bu + a_off + (uint32_t)(mt * 16 * TSTRIDE));   // Ah
#pragma unroll
        for (int mt = 0; mt < 4; mt++)
#pragma unroll
            for (int nt = 0; nt < 4; nt++)
                mma16816(acc[mt][nt], af[mt], &bhf[nt >> 1][(nt & 1) * 2]);
#pragma unroll
        for (int mt = 0; mt < 4; mt++)
#pragma unroll
            for (int nt = 0; nt < 4; nt++)
                mma16816(acc[mt][nt], af[mt], &blf[nt >> 1][(nt & 1) * 2]);
#pragma unroll
        for (int mt = 0; mt < 4; mt++)
            ldsm_x4(af[mt], bu + TILE_B + a_off + (uint32_t)(mt * 16 * TSTRIDE)); // Al
#pragma unroll
        for (int mt = 0; mt < 4; mt++)
#pragma unroll
            for (int nt = 0; nt < 4; nt++)
                mma16816(acc[mt][nt], af[mt], &bhf[nt >> 1][(nt & 1) * 2]);
    }

#pragma unroll
    for (int mt = 0; mt < 4; mt++) {
#pragma unroll
        for (int nt = 0; nt < 4; nt++) {
            const int m0 = bm + warp_m * 64 + mt * 16 + (lane >> 2);
            const int nn = nw + warp_n * 32 + nt * 8 + 2 * (lane & 3);
            const float bb0 = __ldg(bias + nn);
            const float bb1 = __ldg(bias + nn + 1);
#pragma unroll
            for (int half = 0; half < 2; half++) {
                const int m = m0 + half * 8;
                const int bb = m >> 11;
                const int tt = m & (TT - 1);
                const float v0 = (acc[mt][nt][half * 2 + 0] + bb0) * scale;
                const float v1 = (acc[mt][nt][half * 2 + 1] + bb1) * scale;
                if (MODE == 0) {
                    float2 r; r.x = v0; r.y = v1;
                    *(float2*)(Y + (size_t)m * CC + nn) = r;
                } else {
                    const int h = nn >> 6;
                    const int d = nn & (HD - 1);
                    const size_t dst = (size_t)which * MROWS * CC
                                     + (((size_t)bb * HH + h) * TT + tt) * HD + d;
                    uint32_t hw, lw;
                    splitpack(v0, v1, hw, lw);
                    *(uint32_t*)(Yh + dst) = hw;
                    *(uint32_t*)(Yl + dst) = lw;
                }
            }
        }
    }
}

// ---------------------------------------------------------------------------
// flash4: high-occupancy FA2 mma.sync causal attention, split-bf16.
// 128 threads (4 warps x 16 q-rows = 64 q-rows/CTA), 32-key KV tiles,
// 2-stage cp.async, 55KB smem -> 4 CTAs/SM (16 warps/SM). regs <= 128.
// grid (T/64, H, B) = (32, 16, 2).
// ---------------------------------------------------------------------------
#define RS 144
#define FQT_B (64*RS)                  // 9216  (Q hi or lo tile)
#define FKT_B (32*RS)                  // 4608  (one KV subtile)
#define FSTG_B (4*FKT_B)               // 18432 per stage (Kh,Kl,Vh,Vl)
#define FL4_SMEM (2*FQT_B + 2*FSTG_B)  // 55296

__global__ __launch_bounds__(128, 4)
void flash4(const __nv_bfloat16* __restrict__ Qh, const __nv_bfloat16* __restrict__ Ql,
            const __nv_bfloat16* __restrict__ Kh, const __nv_bfloat16* __restrict__ Kl,
            const __nv_bfloat16* __restrict__ Vh, const __nv_bfloat16* __restrict__ Vl)
{
    extern __shared__ char sm[];
    const uint32_t sb = s2u(sm);
    const uint32_t kvb = sb + 2 * FQT_B;

    const int tid = threadIdx.x;
    const int lane = tid & 31;
    const int wid = tid >> 5;              // 0..3
    const int qt = blockIdx.x;             // 0..31 (64-row q block)
    const int h  = blockIdx.y;
    const int b  = blockIdx.z;
    const size_t head = ((size_t)b * HH + h) * TT * HD;

    // ---- issue Q tiles (hi, lo): 1024 x 16B, 8 per thread ----
#pragma unroll
    for (int i = 0; i < 8; i++) {
        const int idx = i * 128 + tid;     // 0..1023
        const int tile = idx >> 9;         // 0..1
        const int row = (idx >> 3) & 63;
        const int seg = idx & 7;
        const __nv_bfloat16* src = (tile == 0) ? Qh : Ql;
        cpa16(sb + tile * FQT_B + row * RS + seg * 16,
              src + head + (size_t)(qt * 64 + row) * HD + seg * 8);
    }
    CP_COMMIT();

    auto issue_kv = [&](int t) {
        const int kv0 = t * 32;
        const uint32_t bu = kvb + (t & 1) * FSTG_B;
#pragma unroll
        for (int i = 0; i < 8; i++) {
            const int idx = i * 128 + tid; // 0..1023
            const int tile = idx >> 8;     // 0..3
            const int row = (idx >> 3) & 31;
            const int seg = idx & 7;
            const __nv_bfloat16* src = (tile == 0) ? Kh : (tile == 1) ? Kl
                                      : (tile == 2) ? Vh : Vl;
            cpa16(bu + tile * FKT_B + row * RS + seg * 16,
                  src + head + (size_t)(kv0 + row) * HD + seg * 8);
        }
        CP_COMMIT();
    };

    const int ntiles = (qt + 1) * 2;       // 32-key tiles
    issue_kv(0);

    // Q group done (one newer group pending)
    CP_WAIT(1);
    __syncthreads();

    uint32_t qhf[4][4], qlf[4][4];
    {
        const uint32_t qaddr = sb + (uint32_t)((wid * 16 + (lane & 15)) * RS
                                               + (lane >> 4) * 16);
#pragma unroll
        for (int ck = 0; ck < 4; ck++) {
            ldsm_x4(qhf[ck], qaddr + ck * 32);
            ldsm_x4(qlf[ck], qaddr + FQT_B + ck * 32);
        }
    }

    float m0 = -1e30f, m1 = -1e30f, l0 = 0.f, l1 = 0.f;
    float oacc[8][4];
#pragma unroll
    for (int nt = 0; nt < 8; nt++)
#pragma unroll
        for (int e = 0; e < 4; e++) oacc[nt][e] = 0.f;

    const int wrow0 = qt * 64 + wid * 16;       // warp's first q row
    const int qrow = wrow0 + (lane >> 2);

    for (int t = 0; t < ntiles; t++) {
        if (t + 1 < ntiles) { issue_kv(t + 1); CP_WAIT(1); }
        else                { CP_WAIT(0); }
        __syncthreads();

        const int kv0 = t * 32;
        const bool active = (kv0 <= wrow0 + 15);   // any unmasked key for this warp

        if (active) {
            const uint32_t bu = kvb + (t & 1) * FSTG_B;

            // ---- S = Q@K^T (3-pass split), 4 n-tiles of 8 keys ----
            float sacc[4][4];
#pragma unroll
            for (int nt = 0; nt < 4; nt++)
#pragma unroll
                for (int e = 0; e < 4; e++) sacc[nt][e] = 0.f;

#pragma unroll
            for (int nt = 0; nt < 4; nt++) {
                const uint32_t ka = bu + (uint32_t)((nt * 8 + (lane & 7)) * RS
                                                    + (lane >> 3) * 16);
                uint32_t khf[8], klf[8];
                ldsm_x4(khf, ka);           ldsm_x4(khf + 4, ka + 64);
                ldsm_x4(klf, ka + FKT_B);   ldsm_x4(klf + 4, ka + FKT_B + 64);
#pragma unroll
                for (int ck = 0; ck < 4; ck++) {
                    mma16816(sacc[nt], qhf[ck], &khf[ck * 2]);
                    mma16816(sacc[nt], qhf[ck], &klf[ck * 2]);
                    mma16816(sacc[nt], qlf[ck], &khf[ck * 2]);
                }
            }

            // ---- causal mask (diagonal warp-tiles) ----
            if (kv0 + 31 > wrow0) {
#pragma unroll
                for (int nt = 0; nt < 4; nt++)
#pragma unroll
                    for (int e = 0; e < 4; e++) {
                        const int key = kv0 + nt * 8 + 2 * (lane & 3) + (e & 1);
                        const int row = qrow + ((e & 2) ? 8 : 0);
                        if (key > row) sacc[nt][e] = -1e30f;
                    }
            }

            // ---- online softmax (rows r and r+8) ----
#pragma unroll
            for (int hh = 0; hh < 2; hh++) {
                float& mprev = hh ? m1 : m0;
                float& lsum  = hh ? l1 : l0;
                float mx = -1e30f;
#pragma unroll
                for (int nt = 0; nt < 4; nt++)
                    mx = fmaxf(mx, fmaxf(sacc[nt][hh*2], sacc[nt][hh*2+1]));
                mx = fmaxf(mx, __shfl_xor_sync(0xffffffffu, mx, 1));
                mx = fmaxf(mx, __shfl_xor_sync(0xffffffffu, mx, 2));
                const float mn = fmaxf(mprev, mx);
                const float alpha = __expf(mprev - mn);
                mprev = mn;
                float ps = 0.f;
#pragma unroll
                for (int nt = 0; nt < 4; nt++) {
                    const float p0 = __expf(sacc[nt][hh*2]   - mn);
                    const float p1 = __expf(sacc[nt][hh*2+1] - mn);
                    ps += p0 + p1;
                    sacc[nt][hh*2]   = p0;
                    sacc[nt][hh*2+1] = p1;
                }
#pragma unroll
                for (int nt = 0; nt < 8; nt++) {
                    oacc[nt][hh*2]   *= alpha;
                    oacc[nt][hh*2+1] *= alpha;
                }
                lsum = lsum * alpha + ps;
            }

            // ---- repack P in place (sacc storage reused as frag storage) ----
            uint32_t* su = (uint32_t*)&sacc[0][0];
#pragma unroll
            for (int ck = 0; ck < 2; ck++) {
                uint32_t h0,l0_,h1,l1_,h2,l2_,h3,l3_;
                splitpack(sacc[2*ck][0],   sacc[2*ck][1],   h0, l0_);
                splitpack(sacc[2*ck][2],   sacc[2*ck][3],   h1, l1_);
                splitpack(sacc[2*ck+1][0], sacc[2*ck+1][1], h2, l2_);
                splitpack(sacc[2*ck+1][2], sacc[2*ck+1][3], h3, l3_);
                su[ck*8+0] = h0; su[ck*8+1] = h1; su[ck*8+2] = h2; su[ck*8+3] = h3;
                su[ck*8+4] = l0_; su[ck*8+5] = l1_; su[ck*8+6] = l2_; su[ck*8+7] = l3_;
            }

            // ---- O += P@V (3-pass split), V via ldmatrix.trans ----
#pragma unroll
            for (int nt = 0; nt < 8; nt++) {
                const uint32_t va = bu + 2 * FKT_B + (uint32_t)(lane * RS + nt * 16);
                uint32_t vhf[4], vlf[4];
                ldsm_x4t(vhf, va);
                ldsm_x4t(vlf, va + FKT_B);
#pragma unroll
                for (int ck = 0; ck < 2; ck++) {
                    mma16816(oacc[nt], &su[ck*8],     &vhf[ck * 2]);  // Ph*Vh
                    mma16816(oacc[nt], &su[ck*8],     &vlf[ck * 2]);  // Ph*Vl
                    mma16816(oacc[nt], &su[ck*8 + 4], &vhf[ck * 2]);  // Pl*Vh
                }
            }
        }
        __syncthreads();   // all warps done with this stage before it is reissued
    }

    // ---- finalize: reduce l across quad, normalize, split-store ----
    l0 += __shfl_xor_sync(0xffffffffu, l0, 1);
    l0 += __shfl_xor_sync(0xffffffffu, l0, 2);
    l1 += __shfl_xor_sync(0xffffffffu, l1, 1);
    l1 += __shfl_xor_sync(0xffffffffu, l1, 2);
    const float inv0 = 1.f / l0;
    const float inv1 = 1.f / l1;

#pragma unroll
    for (int nt = 0; nt < 8; nt++) {
        const int d = nt * 8 + 2 * (lane & 3);
#pragma unroll
        for (int hh = 0; hh < 2; hh++) {
            const int row = qrow + hh * 8;
            const float inv = hh ? inv1 : inv0;
            const float v0 = oacc[nt][hh*2]   * inv;
            const float v1 = oacc[nt][hh*2+1] * inv;
            uint32_t hw, lw;
            splitpack(v0, v1, hw, lw);
            const size_t dst = ((size_t)(b * TT + row)) * CC + h * HD + d;
            *(uint32_t*)(g_aoh + dst) = hw;
            *(uint32_t*)(g_aol + dst) = lw;
        }
    }
}

// ---------------------------------------------------------------------------
extern "C" void kernel_launch(void* const* d_in, const int* in_sizes, int n_in,
                              void* d_out, int out_size)
{
    const float* x  = (const float*)d_in[0];
    const float* Wq = (const float*)d_in[1];
    const float* bq = (const float*)d_in[2];
    const float* Wk = (const float*)d_in[3];
    const float* bk = (const float*)d_in[4];
    const float* Wv = (const float*)d_in[5];
    const float* bv = (const float*)d_in[6];
    const float* Wo = (const float*)d_in[7];
    const float* bo = (const float*)d_in[8];
    float* out = (float*)d_out;

    __nv_bfloat16 *xh, *xl, *qkvh, *qkvl, *aoh, *aol, *wt;
    cudaGetSymbolAddress((void**)&xh,   g_xh);
    cudaGetSymbolAddress((void**)&xl,   g_xl);
    cudaGetSymbolAddress((void**)&qkvh, g_qkvh);
    cudaGetSymbolAddress((void**)&qkvl, g_qkvl);
    cudaGetSymbolAddress((void**)&aoh,  g_aoh);
    cudaGetSymbolAddress((void**)&aol,  g_aol);
    cudaGetSymbolAddress((void**)&wt,   g_wt);

    static bool attr_set = false;
    if (!attr_set) {
        cudaFuncSetAttribute(mmagemm<0>, cudaFuncAttributeMaxDynamicSharedMemorySize, GEMM_SMEM);
        cudaFuncSetAttribute(mmagemm<1>, cudaFuncAttributeMaxDynamicSharedMemorySize, GEMM_SMEM);
        cudaFuncSetAttribute(flash4, cudaFuncAttributeMaxDynamicSharedMemorySize, FL4_SMEM);
        attr_set = true;
    }

    const int n4 = MROWS * CC / 4;
    splitx<<<n4 / 256, 256>>>(x, xh, xl);

    dim3 wgrid(CC / 32, CC / 32, 4);
    wsplit4<<<wgrid, 256>>>(Wq, Wk, Wv, Wo, wt);

    // fused QKV projection (N = 3072), CTA tile 128x128
    dim3 qkv_grid(3 * CC / 128, MROWS / 128);   // (24, 32)
    mmagemm<1><<<qkv_grid, 256, GEMM_SMEM>>>(xh, xl, wt, bq, bk, bv,
                                             nullptr, qkvh, qkvl);

    dim3 att_grid(TT / 64, HH, BB);             // (32, 16, 2)
    flash4<<<att_grid, 128, FL4_SMEM>>>(qkvh, qkvl,
                                        qkvh + (size_t)MROWS*CC, qkvl + (size_t)MROWS*CC,
                                        qkvh + 2*(size_t)MROWS*CC, qkvl + 2*(size_t)MROWS*CC);

    // output projection (N = 1024)
    dim3 out_grid(CC / 128, MROWS / 128);       // (8, 32)
    mmagemm<0><<<out_grid, 256, GEMM_SMEM>>>(aoh, aol, wt + 6*(size_t)CC*CC,
                                             bo, nullptr, nullptr,
                                             out, nullptr, nullptr);
}